// round 5
// baseline (speedup 1.0000x reference)
#include <cuda_runtime.h>
#include <cstdint>

#define NGRP    256          // 4096 / 16 batches per block
#define B_PER   16
#define T_TOT   512
#define TILE_T  16
#define NTILE   32
#define RS      4            // gate-ring slots
#define NTHREADS 288         // 4 stage + 4 gate + 1 consumer warps

#define XROW4       104                      // float4 per xbuf row (100 data + pad, mult of 8)
#define XBUF_F4     (2 * B_PER * XROW4)      // 3328 float4 = 52 KB
#define RING_FLOATS (RS * TILE_T * 128)      // 8192 floats = 32 KB
#define SMEM_BYTES  (RING_FLOATS * 4 + XBUF_F4 * 16)   // 84 KB -> 2 CTAs/SM

__device__ __forceinline__ float tanha(float v) {
    float y;
    asm("tanh.approx.f32 %0, %1;" : "=f"(y) : "f"(v));
    return y;
}

__device__ __forceinline__ uint32_t smem_u32(const void* p) {
    uint32_t a;
    asm("{ .reg .u64 t; cvta.to.shared.u64 t, %1; cvt.u32.u64 %0, t; }" : "=r"(a) : "l"(p));
    return a;
}

#define MBAR_INIT(addr, cnt) \
    asm volatile("mbarrier.init.shared.b64 [%0], %1;" :: "r"(addr), "r"(cnt) : "memory")
#define MBAR_ARRIVE(addr) \
    asm volatile("mbarrier.arrive.release.cta.shared::cta.b64 _, [%0];" :: "r"(addr) : "memory")

__device__ __forceinline__ void mbar_wait_parity(uint32_t mbar, uint32_t parity) {
    uint32_t done;
    asm volatile(
        "{\n\t.reg .pred p;\n\t"
        "mbarrier.try_wait.parity.acquire.cta.shared::cta.b64 p, [%1], %2;\n\t"
        "selp.b32 %0, 1, 0, p;\n\t}"
        : "=r"(done) : "r"(mbar), "r"(parity) : "memory");
    if (!done) {
        asm volatile(
            "{\n\t.reg .pred P1;\n\t"
            "W_%=:\n\t"
            "mbarrier.try_wait.parity.acquire.cta.shared::cta.b64 P1, [%0], %1, 0x989680;\n\t"
            "@P1 bra.uni D_%=;\n\t"
            "bra.uni W_%=;\n\t"
            "D_%=:\n\t}"
            :: "r"(mbar), "r"(parity) : "memory");
    }
}

// ---------------------------------------------------------------------------
// Gate work: one warp per (LSTM L, t-half th). lane = (sub<<4)|b:
// b = batch 0..15, sub picks t-quad. Thread computes 4 timesteps
// tloc = th*8 + sub*4 + i (i=0..3). Since tbase % 4 == 0 and FOFF % 4 == 0,
// the float4-window offset o == i is compile-time: no dynamic xa[] indexing.
// ---------------------------------------------------------------------------
template <int NF>
__device__ __forceinline__ void gate_loop(
    const float4* __restrict__ xb4, float* __restrict__ ring,
    uint32_t full_base, uint32_t empty_base,
    int lane, int th, const float* __restrict__ Wih, const float* __restrict__ bp)
{
    constexpr int FOFF = (NF == 13) ? 12 : 0;
    constexpr int LOFF = (NF == 13) ? 64 : 0;

    float w[4][13], bb[4];
    #pragma unroll
    for (int g = 0; g < 4; g++) {
        float sc = (g == 2) ? 1.0f : 0.5f;
        bb[g] = bp[g] * sc;
        #pragma unroll
        for (int f = 0; f < NF; f++) w[g][f] = Wih[g * NF + f] * sc;
    }

    const int b    = lane & 15;
    const int sub  = lane >> 4;
    const int tbase = th * 8 + sub * 4;
    const int xl   = b & 7;

    asm volatile("bar.sync 1, 256;" ::: "memory");   // prologue stage done

    for (int k = 0; k < NTILE; k++) {
        const int s = k & (RS - 1);
        mbar_wait_parity(empty_base + s * 8, 1u ^ ((k >> 2) & 1));

        const float4* xr = xb4 + (size_t)((k & 1) * B_PER + b) * XROW4;

        #pragma unroll
        for (int i = 0; i < 4; i++) {
            const int tloc = tbase + i;
            const int q0 = (tloc * 25 + FOFF) >> 2;     // window start (o == i)
            constexpr int NQ[4] = { (0 + NF + 3) >> 2, (1 + NF + 3) >> 2,
                                    (2 + NF + 3) >> 2, (3 + NF + 3) >> 2 };

            float xa[16];
            #pragma unroll
            for (int j = 0; j < 4; j++) {
                if (j < NQ[i]) {
                    float4 t = xr[(q0 + j) ^ xl];
                    xa[4 * j + 0] = t.x; xa[4 * j + 1] = t.y;
                    xa[4 * j + 2] = t.z; xa[4 * j + 3] = t.w;
                }
            }

            float a0 = bb[0], a1 = bb[1], a2 = bb[2], a3 = bb[3];
            #pragma unroll
            for (int f = 0; f < NF; f++) {
                float v = xa[i + f];
                a0 = fmaf(w[0][f], v, a0);
                a1 = fmaf(w[1][f], v, a1);
                a2 = fmaf(w[2][f], v, a2);
                a3 = fmaf(w[3][f], v, a3);
            }

            *(float4*)(ring + (size_t)(s * TILE_T + tloc) * 128 + LOFF + b * 4) =
                make_float4(a0, a1, a2, a3);
        }

        MBAR_ARRIVE(full_base + s * 8);
        asm volatile("bar.sync 1, 256;" ::: "memory");
    }
}

// ---------------------------------------------------------------------------
__global__ __launch_bounds__(NTHREADS, 2) void fused_kernel(
    const float* __restrict__ x,
    const float* __restrict__ Wih1, const float* __restrict__ Whh1, const float* __restrict__ b1,
    const float* __restrict__ Wih2, const float* __restrict__ Whh2, const float* __restrict__ b2,
    const float* __restrict__ Wout, const float* __restrict__ bout,
    float* __restrict__ out)
{
    extern __shared__ float smem[];
    float*  ring = smem;                             // [RS][TILE_T][128]
    float4* xb4  = (float4*)(smem + RING_FLOATS);    // [2][B_PER][XROW4]

    __shared__ __align__(8) uint64_t bars[2 * RS];

    const int tid = threadIdx.x;
    const int wid = tid >> 5;
    const int bg  = blockIdx.x;

    const uint32_t full_base  = smem_u32(bars);
    const uint32_t empty_base = full_base + RS * 8;

    if (tid == 0) {
        #pragma unroll
        for (int s = 0; s < RS; s++) {
            MBAR_INIT(full_base  + s * 8, 128);   // gate threads
            MBAR_INIT(empty_base + s * 8, 32);    // consumer threads
        }
    }
    __syncthreads();

    if (wid < 4) {
        // ================= STAGE WARPS: float4 LDG -> swizzled float4 STS =====
        const int sj = tid;                           // 0..127
        const float4* xg = (const float4*)x;
        const size_t rowbase = (size_t)bg * B_PER * 3200;   // 3200 f4 per batch row

        float4 rb[2][13];

        // 1600 f4 per tile (16 b x 100 f4) over 128 threads -> 13 iters (last half-masked)
        #define LDG_TILE(K, R) do {                                               \
            _Pragma("unroll")                                                     \
            for (int m = 0; m < 13; m++) {                                        \
                int i = m * 128 + sj;                                             \
                if (m < 12 || sj < 64) {                                          \
                    int b = i / 100, q = i - b * 100;                             \
                    (R)[m] = xg[rowbase + (size_t)b * 3200 + (size_t)(K) * 100 + q]; \
                }                                                                 \
            } } while (0)

        #define STS_TILE(BUF, R) do {                                             \
            float4* dst = xb4 + (size_t)(BUF) * B_PER * XROW4;                    \
            _Pragma("unroll")                                                     \
            for (int m = 0; m < 13; m++) {                                        \
                int i = m * 128 + sj;                                             \
                if (m < 12 || sj < 64) {                                          \
                    int b = i / 100, q = i - b * 100;                             \
                    dst[(size_t)b * XROW4 + (q ^ (b & 7))] = (R)[m];              \
                }                                                                 \
            } } while (0)

        LDG_TILE(0, rb[0]);
        STS_TILE(0, rb[0]);
        asm volatile("bar.sync 1, 256;" ::: "memory");
        LDG_TILE(1, rb[1]);

        for (int k = 0; k < NTILE; k++) {
            if (k < NTILE - 1) {
                STS_TILE(1 - (k & 1), rb[(k + 1) & 1]);
                asm volatile("bar.sync 1, 256;" ::: "memory");
                if (k < NTILE - 2) LDG_TILE(k + 2, rb[k & 1]);
            } else {
                asm volatile("bar.sync 1, 256;" ::: "memory");
            }
        }
        #undef LDG_TILE
        #undef STS_TILE
    } else if (wid < 8) {
        // ================= GATE WARPS =========================================
        const int gw = wid - 4;
        const int L  = gw & 1;       // 0: LSTM1, 1: LSTM2
        const int th = gw >> 1;      // t-half 0..1
        const int lane = tid & 31;
        if (L == 0) gate_loop<12>(xb4, ring, full_base, empty_base, lane, th, Wih1, b1);
        else        gate_loop<13>(xb4, ring, full_base, empty_base, lane, th, Wih2, b2);
    } else {
        // ================= CONSUMER: one warp, both LSTMs =====================
        const int lane = tid & 31;
        const int L    = lane >> 4;   // 0: LSTM1, 1: LSTM2
        const int b    = lane & 15;

        const float* Whh = L ? Whh2 : Whh1;
        const float whi = Whh[0] * 0.5f;
        const float whf = Whh[1] * 0.5f;
        const float whg = Whh[2];
        const float who = Whh[3] * 0.5f;

        float h = 0.0f, c = 0.0f;

        for (int k = 0; k < NTILE; k++) {
            const int s = k & (RS - 1);
            mbar_wait_parity(full_base + s * 8, (k >> 2) & 1);

            const float4* zp = (const float4*)&ring[(size_t)(s * TILE_T) * 128 + L * 64 + b * 4];
            float4 z = zp[0];
            #pragma unroll
            for (int d = 0; d < TILE_T; d++) {
                float4 zn = z;
                if (d + 1 < TILE_T) zn = zp[(d + 1) * 32];

                float zi = fmaf(whi, h, z.x);
                float zf = fmaf(whf, h, z.y);
                float zg = fmaf(whg, h, z.z);
                float zo = fmaf(who, h, z.w);

                float gi = fmaf(0.5f, tanha(zi), 0.5f);
                float gf = fmaf(0.5f, tanha(zf), 0.5f);
                float gg = tanha(zg);
                float go = fmaf(0.5f, tanha(zo), 0.5f);

                c = fmaf(gf, c, gi * gg);
                h = go * tanha(c);
                z = zn;
            }
            MBAR_ARRIVE(empty_base + s * 8);
        }

        float other = __shfl_xor_sync(0xffffffffu, h, 16);
        if (L == 0) {
            float y = fmaf(Wout[0], h, fmaf(Wout[1], other, bout[0]));
            out[bg * B_PER + b] = 1.0f / (1.0f + __expf(-y));
        }
    }
}

// ---------------------------------------------------------------------------
extern "C" void kernel_launch(void* const* d_in, const int* in_sizes, int n_in,
                              void* d_out, int out_size)
{
    const float* x    = (const float*)d_in[0];
    const float* Wih1 = (const float*)d_in[1];
    const float* Whh1 = (const float*)d_in[2];
    const float* b1   = (const float*)d_in[3];
    const float* Wih2 = (const float*)d_in[4];
    const float* Whh2 = (const float*)d_in[5];
    const float* b2   = (const float*)d_in[6];
    const float* Wout = (const float*)d_in[7];
    const float* bout = (const float*)d_in[8];

    cudaFuncSetAttribute(fused_kernel, cudaFuncAttributeMaxDynamicSharedMemorySize, SMEM_BYTES);
    fused_kernel<<<NGRP, NTHREADS, SMEM_BYTES>>>(
        x, Wih1, Whh1, b1, Wih2, Whh2, b2, Wout, bout, (float*)d_out);
}

// round 6
// speedup vs baseline: 2.0123x; 2.0123x over previous
#include <cuda_runtime.h>
#include <cstdint>

#define NGRP    128
#define T_TOT   512
#define TILE_T  16
#define NTILE   32
#define XS      3            // xbuf slots (cp.async triple buffer)
#define RS      2            // gate-ring slots
#define PROD_T  512
#define CONS_T  64
#define NTHREADS 576

#define XROW4       104                      // float4 per xbuf row (100 data + pad, mult of 8)
#define XSLOT_F4    (32 * XROW4)             // 3328 float4 per slot
#define RING_FLOATS (RS * TILE_T * 256)      // 8192 floats = 32 KB
#define SMEM_BYTES  (RING_FLOATS * 4 + XS * XSLOT_F4 * 16)   // 192.5 KB

__device__ __forceinline__ float tanha(float v) {
    float y;
    asm("tanh.approx.f32 %0, %1;" : "=f"(y) : "f"(v));
    return y;
}

__device__ __forceinline__ uint32_t smem_u32(const void* p) {
    uint32_t a;
    asm("{ .reg .u64 t; cvta.to.shared.u64 t, %1; cvt.u32.u64 %0, t; }" : "=r"(a) : "l"(p));
    return a;
}

#define MBAR_INIT(addr, cnt) \
    asm volatile("mbarrier.init.shared.b64 [%0], %1;" :: "r"(addr), "r"(cnt) : "memory")
#define MBAR_ARRIVE(addr) \
    asm volatile("mbarrier.arrive.release.cta.shared::cta.b64 _, [%0];" :: "r"(addr) : "memory")

__device__ __forceinline__ void mbar_wait_parity(uint32_t mbar, uint32_t parity) {
    uint32_t done;
    asm volatile(
        "{\n\t.reg .pred p;\n\t"
        "mbarrier.try_wait.parity.acquire.cta.shared::cta.b64 p, [%1], %2;\n\t"
        "selp.b32 %0, 1, 0, p;\n\t}"
        : "=r"(done) : "r"(mbar), "r"(parity) : "memory");
    if (!done) {
        asm volatile(
            "{\n\t.reg .pred P1;\n\t"
            "W_%=:\n\t"
            "mbarrier.try_wait.parity.acquire.cta.shared::cta.b64 P1, [%0], %1, 0x989680;\n\t"
            "@P1 bra.uni D_%=;\n\t"
            "bra.uni W_%=;\n\t"
            "D_%=:\n\t}"
            :: "r"(mbar), "r"(parity) : "memory");
    }
}

#define CP_ASYNC16(dst_u32, src_ptr) \
    asm volatile("cp.async.cg.shared.global [%0], [%1], 16;" \
                 :: "r"(dst_u32), "l"(src_ptr) : "memory")
#define CP_COMMIT()  asm volatile("cp.async.commit_group;" ::: "memory")
#define CP_WAIT(N)   asm volatile("cp.async.wait_group %0;" :: "n"(N) : "memory")

// ---------------------------------------------------------------------------
// Gate warps: one warp per (LSTM L, t-quad tq). lane = batch; thread computes
// 4 timesteps (tq*4+i) x 4 gates from swizzled xbuf; writes float4 to ring.
// ---------------------------------------------------------------------------
template <int NF>
__device__ __forceinline__ void gate_loop(
    const float4* __restrict__ xb4, float* __restrict__ ring,
    uint32_t full_base, uint32_t empty_base,
    int l, int tq, const float* __restrict__ Wih, const float* __restrict__ bp)
{
    constexpr int FOFF = (NF == 13) ? 12 : 0;
    constexpr int LOFF = (NF == 13) ? 128 : 0;

    float w[4][13], bb[4];
    #pragma unroll
    for (int g = 0; g < 4; g++) {
        float sc = (g == 2) ? 1.0f : 0.5f;
        bb[g] = bp[g] * sc;
        #pragma unroll
        for (int f = 0; f < NF; f++) w[g][f] = Wih[g * NF + f] * sc;
    }

    const int xl  = l & 7;
    const int tq4 = tq * 4;

    asm volatile("bar.sync 1, %0;" :: "n"(PROD_T) : "memory");  // prologue: tile 0 landed

    int xs = 0;                      // xbuf slot = k % 3
    for (int k = 0; k < NTILE; k++) {
        const int s = k & (RS - 1);
        mbar_wait_parity(empty_base + s * 8, 1u ^ ((k >> 1) & 1));

        const float4* xr = xb4 + (size_t)(xs * 32 + l) * XROW4;

        #pragma unroll
        for (int i = 0; i < 4; i++) {
            const int tloc = tq4 + i;
            const int q0 = (tloc * 25 + FOFF) >> 2;   // window start; offset == i
            const int nq = (i + NF + 3) >> 2;

            float xa[16];
            #pragma unroll
            for (int j = 0; j < 4; j++) {
                if (j < nq) {
                    float4 t = xr[(q0 + j) ^ xl];
                    xa[4 * j + 0] = t.x; xa[4 * j + 1] = t.y;
                    xa[4 * j + 2] = t.z; xa[4 * j + 3] = t.w;
                }
            }

            float a0 = bb[0], a1 = bb[1], a2 = bb[2], a3 = bb[3];
            #pragma unroll
            for (int f = 0; f < NF; f++) {
                float v = xa[i + f];
                a0 = fmaf(w[0][f], v, a0);
                a1 = fmaf(w[1][f], v, a1);
                a2 = fmaf(w[2][f], v, a2);
                a3 = fmaf(w[3][f], v, a3);
            }

            *(float4*)(ring + (size_t)(s * TILE_T + tloc) * 256 + LOFF + l * 4) =
                make_float4(a0, a1, a2, a3);
        }

        MBAR_ARRIVE(full_base + s * 8);
        asm volatile("bar.sync 1, %0;" :: "n"(PROD_T) : "memory");
        if (++xs == XS) xs = 0;
    }
}

// ---------------------------------------------------------------------------
__global__ __launch_bounds__(NTHREADS, 1) void fused_kernel(
    const float* __restrict__ x,
    const float* __restrict__ Wih1, const float* __restrict__ Whh1, const float* __restrict__ b1,
    const float* __restrict__ Wih2, const float* __restrict__ Whh2, const float* __restrict__ b2,
    const float* __restrict__ Wout, const float* __restrict__ bout,
    float* __restrict__ out)
{
    extern __shared__ float smem[];
    float*  ring = smem;                             // [RS][TILE_T][256]
    float4* xb4  = (float4*)(smem + RING_FLOATS);    // [XS][32][XROW4]

    __shared__ __align__(8) uint64_t bars[2 * RS];
    __shared__ float h2s[32];

    const int tid = threadIdx.x;
    const int wid = tid >> 5;
    const int bg  = blockIdx.x;

    const uint32_t full_base  = smem_u32(bars);
    const uint32_t empty_base = full_base + RS * 8;

    if (tid == 0) {
        #pragma unroll
        for (int s = 0; s < RS; s++) {
            MBAR_INIT(full_base  + s * 8, 256);   // gate threads
            MBAR_INIT(empty_base + s * 8, CONS_T);
        }
    }
    __syncthreads();

    if (wid < 8) {
        // ===== STAGE WARPS: cp.async GMEM -> swizzled SMEM (no reg transit) ===
        const int sj = tid;                               // 0..255
        const float4* xg = (const float4*)x;
        const size_t rowbase = (size_t)bg * 32 * 3200;    // f4 per batch row
        const uint32_t xb_base = smem_u32(xb4);

        // per-thread precomputed (b, q) pairs for the 13-iteration mapping
        int bidx[13], dsto[13], srco[13];
        #pragma unroll
        for (int m = 0; m < 13; m++) {
            int i = m * 256 + sj;
            int b = i / 100, q = i - b * 100;
            bidx[m] = b;
            dsto[m] = b * XROW4 + (q ^ (b & 7));          // f4 units within slot
            srco[m] = b * 3200 + q;                       // f4 units within group, + k*100
        }

        #define ISSUE_TILE(K, SLOT) do {                                          \
            uint32_t dbase = xb_base + (uint32_t)(SLOT) * (XSLOT_F4 * 16);        \
            _Pragma("unroll")                                                     \
            for (int m = 0; m < 13; m++) {                                        \
                if (m < 12 || sj < 128) {                                         \
                    CP_ASYNC16(dbase + (uint32_t)dsto[m] * 16,                    \
                               xg + rowbase + srco[m] + (K) * 100);               \
                }                                                                 \
            }                                                                     \
            CP_COMMIT();                                                          \
        } while (0)

        ISSUE_TILE(0, 0);
        ISSUE_TILE(1, 1);
        CP_WAIT(1);                                       // tile 0 landed
        asm volatile("bar.sync 1, %0;" :: "n"(PROD_T) : "memory");

        int slot = 2;                                     // slot for tile k+2
        for (int k = 0; k < NTILE; k++) {
            if (k + 2 < NTILE) {
                ISSUE_TILE(k + 2, slot);
                CP_WAIT(1);                               // tile k+1 landed
            } else if (k + 1 < NTILE) {
                CP_WAIT(0);                               // tail: all landed
            }
            asm volatile("bar.sync 1, %0;" :: "n"(PROD_T) : "memory");
            if (++slot == XS) slot = 0;
        }
        #undef ISSUE_TILE
    } else if (wid < 16) {
        // ===== GATE WARPS ====================================================
        const int gw = wid - 8;
        const int L  = gw & 1;       // 0: LSTM1, 1: LSTM2
        const int tq = gw >> 1;      // t-quad 0..3
        const int l  = tid & 31;     // batch lane
        if (L == 0) gate_loop<12>(xb4, ring, full_base, empty_base, l, tq, Wih1, b1);
        else        gate_loop<13>(xb4, ring, full_base, empty_base, l, tq, Wih2, b2);
    } else {
        // ===== CONSUMER: serial recurrence ===================================
        const int ctid = tid - PROD_T;
        const int cw   = ctid >> 5;  // 0: LSTM1, 1: LSTM2
        const int lane = ctid & 31;

        const float* Whh = cw ? Whh2 : Whh1;
        const float whi = Whh[0] * 0.5f;
        const float whf = Whh[1] * 0.5f;
        const float whg = Whh[2];
        const float who = Whh[3] * 0.5f;

        float h = 0.0f, c = 0.0f;

        for (int k = 0; k < NTILE; k++) {
            const int s = k & (RS - 1);
            mbar_wait_parity(full_base + s * 8, (k >> 1) & 1);

            const float4* zp = (const float4*)&ring[(size_t)(s * TILE_T) * 256 + cw * 128 + lane * 4];
            float4 z = zp[0];
            #pragma unroll
            for (int d = 0; d < TILE_T; d++) {
                float4 zn = z;
                if (d + 1 < TILE_T) zn = zp[(d + 1) * 64];

                float zi = fmaf(whi, h, z.x);
                float zf = fmaf(whf, h, z.y);
                float zg = fmaf(whg, h, z.z);
                float zo = fmaf(who, h, z.w);

                float gi = fmaf(0.5f, tanha(zi), 0.5f);
                float gf = fmaf(0.5f, tanha(zf), 0.5f);
                float gg = tanha(zg);
                float go = fmaf(0.5f, tanha(zo), 0.5f);

                c = fmaf(gf, c, gi * gg);
                h = go * tanha(c);
                z = zn;
            }
            MBAR_ARRIVE(empty_base + s * 8);
        }

        if (cw == 1) h2s[lane] = h;
        asm volatile("bar.sync 2, %0;" :: "n"(CONS_T) : "memory");
        if (cw == 0) {
            float h2 = h2s[lane];
            float y = fmaf(Wout[0], h, fmaf(Wout[1], h2, bout[0]));
            out[bg * 32 + lane] = 1.0f / (1.0f + __expf(-y));
        }
    }
}

// ---------------------------------------------------------------------------
extern "C" void kernel_launch(void* const* d_in, const int* in_sizes, int n_in,
                              void* d_out, int out_size)
{
    const float* x    = (const float*)d_in[0];
    const float* Wih1 = (const float*)d_in[1];
    const float* Whh1 = (const float*)d_in[2];
    const float* b1   = (const float*)d_in[3];
    const float* Wih2 = (const float*)d_in[4];
    const float* Whh2 = (const float*)d_in[5];
    const float* b2   = (const float*)d_in[6];
    const float* Wout = (const float*)d_in[7];
    const float* bout = (const float*)d_in[8];

    cudaFuncSetAttribute(fused_kernel, cudaFuncAttributeMaxDynamicSharedMemorySize, SMEM_BYTES);
    fused_kernel<<<NGRP, NTHREADS, SMEM_BYTES>>>(
        x, Wih1, Whh1, b1, Wih2, Whh2, b2, Wout, bout, (float*)d_out);
}